// round 9
// baseline (speedup 1.0000x reference)
#include <cuda_runtime.h>
#include <cuda_bf16.h>
#include <math.h>
#include <stdint.h>

#define T_LEN   512
#define B_SZ    128
#define H_SZ    1024
#define NIN     128
#define NOUT    128
#define ALPHA_F 0.25f
#define LEAK_F  0.75f
#define NSCALE  0.025f
#define GRID_RNN 128

// rnn SMEM: A tile 128 rows x 528B pitch, hi + lo
#define PITCH   528
#define A_HI    0
#define A_LO    67584
#define SM_ALLOC 135168

// tensorized post kernel SMEM
#define P_AH   0
#define P_AL   67584
#define P_BH   135168
#define P_BL   168960
#define P_SMEM 202752

// ---------------- device scratch ----------------
__device__ float g_c[(size_t)T_LEN * B_SZ * H_SZ];
__device__ __nv_bfloat16 g_a_hi[B_SZ * H_SZ];
__device__ __nv_bfloat16 g_a_lo[B_SZ * H_SZ];
__device__ float g_p[8 * B_SZ * H_SZ];               // 8 split-K partials
__device__ unsigned g_bar_count;
__device__ unsigned g_rel[GRID_RNN * 32];

__device__ __forceinline__ void mma_bf16(float& c0, float& c1, float& c2, float& c3,
                                         uint32_t a0, uint32_t a1, uint32_t a2, uint32_t a3,
                                         uint32_t b0, uint32_t b1) {
    asm volatile(
        "mma.sync.aligned.m16n8k16.row.col.f32.bf16.bf16.f32 "
        "{%0,%1,%2,%3}, {%4,%5,%6,%7}, {%8,%9}, {%0,%1,%2,%3};"
        : "+f"(c0), "+f"(c1), "+f"(c2), "+f"(c3)
        : "r"(a0), "r"(a1), "r"(a2), "r"(a3), "r"(b0), "r"(b1));
}

__device__ __forceinline__ uint32_t pack_bf16(float a, float b) {
    __nv_bfloat16 x = __float2bfloat16(a), y = __float2bfloat16(b);
    return (uint32_t)__bfloat16_as_ushort(x) | ((uint32_t)__bfloat16_as_ushort(y) << 16);
}

// ---------------- init ----------------
__global__ void init_kernel(const float* __restrict__ hidden) {
    int i = blockIdx.x * blockDim.x + threadIdx.x;
    if (i == 0) g_bar_count = 0u;
    if (i < GRID_RNN * 32) g_rel[i] = 0u;
    if (i < B_SZ * H_SZ) {
        float t = tanhf(hidden[i]);
        __nv_bfloat16 hi = __float2bfloat16(t);
        g_a_hi[i] = hi;
        g_a_lo[i] = __float2bfloat16(t - __bfloat162float(hi));
    }
}

// ---------------- pre (unchanged scalar) ----------------
__global__ void __launch_bounds__(256) pre_kernel(
    const float* __restrict__ x, const float* __restrict__ noise,
    const float* __restrict__ w_in, const float* __restrict__ b_in,
    const float* __restrict__ b_hh)
{
    __shared__ float As[16][68];
    __shared__ float Bs[16][68];
    int tid = threadIdx.x;
    int tr = tid >> 4, tc = tid & 15;
    int lr = tid >> 2, lk = (tid & 3) * 4;
    int r0 = blockIdx.x * 64, c0 = blockIdx.y * 64;
    float acc[4][4] = {};
    int rA = r0 + lr, tt = rA >> 7, bb = rA & 127;
    const float* arow = x + ((size_t)bb * T_LEN + tt) * NIN;
    const float* brow = w_in + (size_t)(c0 + lr) * NIN;
    for (int ko = 0; ko < NIN; ko += 16) {
        float4 av = *(const float4*)(arow + ko + lk);
        float4 bv = *(const float4*)(brow + ko + lk);
        __syncthreads();
        As[lk + 0][lr] = av.x; As[lk + 1][lr] = av.y; As[lk + 2][lr] = av.z; As[lk + 3][lr] = av.w;
        Bs[lk + 0][lr] = bv.x; Bs[lk + 1][lr] = bv.y; Bs[lk + 2][lr] = bv.z; Bs[lk + 3][lr] = bv.w;
        __syncthreads();
        #pragma unroll
        for (int kk = 0; kk < 16; kk++) {
            float a[4], b[4];
            *(float4*)a = *(float4*)&As[kk][tr * 4];
            *(float4*)b = *(float4*)&Bs[kk][tc * 4];
            #pragma unroll
            for (int i = 0; i < 4; i++)
                #pragma unroll
                for (int j = 0; j < 4; j++) acc[i][j] = fmaf(a[i], b[j], acc[i][j]);
        }
    }
    int c = c0 + tc * 4;
    float bi0 = b_in[c] + b_hh[c], bi1 = b_in[c + 1] + b_hh[c + 1];
    float bi2 = b_in[c + 2] + b_hh[c + 2], bi3 = b_in[c + 3] + b_hh[c + 3];
    #pragma unroll
    for (int i = 0; i < 4; i++) {
        size_t off = (size_t)(r0 + tr * 4 + i) * H_SZ + c;
        float4 nv = *(const float4*)(noise + off);
        float4 v;
        v.x = ALPHA_F * (acc[i][0] + bi0) + NSCALE * nv.x;
        v.y = ALPHA_F * (acc[i][1] + bi1) + NSCALE * nv.y;
        v.z = ALPHA_F * (acc[i][2] + bi2) + NSCALE * nv.z;
        v.w = ALPHA_F * (acc[i][3] + bi3) + NSCALE * nv.w;
        *(float4*)(g_c + off) = v;
    }
}

// ---- grid barrier: atomic arrival + per-CTA-line release (proven R7) ------
__device__ __forceinline__ void grid_bar(int cta, unsigned epoch, unsigned* smflag) {
    __syncthreads();
    if (threadIdx.x == 0) {
        __threadfence();
        unsigned arrived = atomicAdd(&g_bar_count, 1u) + 1u;
        *smflag = (arrived == epoch * (unsigned)GRID_RNN) ? 1u : 0u;
    }
    __syncthreads();
    if (*smflag) {
        if (threadIdx.x < GRID_RNN) {
            *(volatile unsigned*)&g_rel[threadIdx.x * 32] = epoch;
        }
    } else if (threadIdx.x == 0) {
        while (*(volatile unsigned*)&g_rel[cta * 32] < epoch) { }
        __threadfence();
    }
    __syncthreads();
}

// --------- persistent recurrent kernel: register-resident weights ------------
// 128 CTAs = 8 k-splits x 16 h-tiles. CTA tile M=128,N=64,K=128.
// 8 warps of 32x32; B (weights, bf16 hi/lo) lives in registers for all steps.
__global__ void __launch_bounds__(256, 1) rnn_kernel(
    float* __restrict__ hid_list, float* __restrict__ h_final,
    const float* __restrict__ w_hh, const float* __restrict__ hidden0)
{
    extern __shared__ char sm[];
    __shared__ unsigned smflag;
    const int cta = blockIdx.x;
    const int ks = cta & 7;
    const int ht = cta >> 3;
    const int tid = threadIdx.x;
    const int c0 = ht * 64, k0 = ks * 128;

    const int wid = tid >> 5, lane = tid & 31;
    const int wm = (wid & 3) * 32;        // warp M offset (128 = 4 stripes)
    const int wn = (wid >> 2) * 32;       // warp N offset (64 = 2 stripes)
    const int gq = lane >> 2;             // 0..7
    const int q  = lane & 3;              // 0..3

    // ---- one-time: stage weight slice to SMEM (hi/lo), load B fragments ----
    for (int e = tid; e < 64 * 128; e += 256) {
        int n = e >> 7, k = e & 127;
        float w = w_hh[(size_t)(c0 + n) * H_SZ + k0 + k];
        __nv_bfloat16 wh = __float2bfloat16(w);
        __nv_bfloat16 wl = __float2bfloat16(w - __bfloat162float(wh));
        *(__nv_bfloat16*)(sm + n * PITCH + k * 2) = wh;
        *(__nv_bfloat16*)(sm + 33792 + n * PITCH + k * 2) = wl;
    }
    __syncthreads();

    uint32_t bh[8][4][2], bl[8][4][2];    // [kt][nt][reg] : 128 regs total
    {
        const char* pB = sm + (wn + gq) * PITCH + q * 4;
        #pragma unroll
        for (int kt = 0; kt < 8; kt++) {
            #pragma unroll
            for (int nt = 0; nt < 4; nt++) {
                const char* p = pB + nt * 8 * PITCH + kt * 32;
                bh[kt][nt][0] = *(const uint32_t*)(p);
                bh[kt][nt][1] = *(const uint32_t*)(p + 16);
                bl[kt][nt][0] = *(const uint32_t*)(p + 33792);
                bl[kt][nt][1] = *(const uint32_t*)(p + 33792 + 16);
            }
        }
    }
    __syncthreads();

    const char* pAh = sm + A_HI + (wm + gq) * PITCH + q * 4;
    const char* pAl = sm + A_LO + (wm + gq) * PITCH + q * 4;
    float* pout = g_p + (size_t)ks * (B_SZ * H_SZ);

    const int e  = cta * 1024 + tid * 4;
    const int eb = e >> 10, eh = e & 1023;
    float4 hreg = *(const float4*)(hidden0 + e);
    unsigned epoch = 0;

    for (int t = 0; t < T_LEN; t++) {
        float4 cv = __ldcg((const float4*)(g_c + (size_t)t * (B_SZ * H_SZ) + e));

        // ---- stage A slice (128 rows x 128 cols, hi+lo) ----
        #pragma unroll
        for (int i = 0; i < 8; i++) {
            int idx = i * 256 + tid;          // 0..2047 uint4 units
            int r = idx >> 4, c16 = idx & 15;
            size_t goff = (size_t)r * 2048 + (size_t)k0 * 2 + c16 * 16;
            uint4 vh = __ldcg((const uint4*)((const char*)g_a_hi + goff));
            uint4 vl = __ldcg((const uint4*)((const char*)g_a_lo + goff));
            *(uint4*)(sm + A_HI + r * PITCH + c16 * 16) = vh;
            *(uint4*)(sm + A_LO + r * PITCH + c16 * 16) = vl;
        }
        __syncthreads();

        // ---- GEMM: B in registers, A from SMEM ----
        float acc[2][4][4] = {};
        #pragma unroll
        for (int kt = 0; kt < 8; kt++) {
            const int kb = kt * 32;
            uint32_t ah[2][4], al[2][4];
            #pragma unroll
            for (int mt = 0; mt < 2; mt++) {
                const int mo = mt * 16 * PITCH;
                ah[mt][0] = *(const uint32_t*)(pAh + mo + kb);
                ah[mt][1] = *(const uint32_t*)(pAh + mo + 8 * PITCH + kb);
                ah[mt][2] = *(const uint32_t*)(pAh + mo + kb + 16);
                ah[mt][3] = *(const uint32_t*)(pAh + mo + 8 * PITCH + kb + 16);
                al[mt][0] = *(const uint32_t*)(pAl + mo + kb);
                al[mt][1] = *(const uint32_t*)(pAl + mo + 8 * PITCH + kb);
                al[mt][2] = *(const uint32_t*)(pAl + mo + kb + 16);
                al[mt][3] = *(const uint32_t*)(pAl + mo + 8 * PITCH + kb + 16);
            }
            #pragma unroll
            for (int mt = 0; mt < 2; mt++)
                #pragma unroll
                for (int nt = 0; nt < 4; nt++) {
                    mma_bf16(acc[mt][nt][0], acc[mt][nt][1], acc[mt][nt][2], acc[mt][nt][3],
                             ah[mt][0], ah[mt][1], ah[mt][2], ah[mt][3],
                             bh[kt][nt][0], bh[kt][nt][1]);
                    mma_bf16(acc[mt][nt][0], acc[mt][nt][1], acc[mt][nt][2], acc[mt][nt][3],
                             ah[mt][0], ah[mt][1], ah[mt][2], ah[mt][3],
                             bl[kt][nt][0], bl[kt][nt][1]);
                    mma_bf16(acc[mt][nt][0], acc[mt][nt][1], acc[mt][nt][2], acc[mt][nt][3],
                             al[mt][0], al[mt][1], al[mt][2], al[mt][3],
                             bh[kt][nt][0], bh[kt][nt][1]);
                }
        }
        // write partials
        #pragma unroll
        for (int mt = 0; mt < 2; mt++)
            #pragma unroll
            for (int nt = 0; nt < 4; nt++) {
                float* pp = pout + (size_t)(wm + mt * 16 + gq) * H_SZ + c0 + wn + nt * 8 + q * 2;
                *(float2*)pp = make_float2(acc[mt][nt][0], acc[mt][nt][1]);
                *(float2*)(pp + 8 * H_SZ) = make_float2(acc[mt][nt][2], acc[mt][nt][3]);
            }

        grid_bar(cta, ++epoch, &smflag);

        // ---- update: h' = 0.75h + 0.25*sum(8 partials) + c[t] ----
        {
            float4 s0 = *(const float4*)(g_p + e);
            #pragma unroll
            for (int s = 1; s < 8; s++) {
                float4 ps = *(const float4*)(g_p + (size_t)s * (B_SZ * H_SZ) + e);
                s0.x += ps.x; s0.y += ps.y; s0.z += ps.z; s0.w += ps.w;
            }
            float4 hn;
            hn.x = LEAK_F * hreg.x + ALPHA_F * s0.x + cv.x;
            hn.y = LEAK_F * hreg.y + ALPHA_F * s0.y + cv.y;
            hn.z = LEAK_F * hreg.z + ALPHA_F * s0.z + cv.z;
            hn.w = LEAK_F * hreg.w + ALPHA_F * s0.w + cv.w;
            hreg = hn;
            *(float4*)(hid_list + ((size_t)eb * T_LEN + t) * H_SZ + eh) = hn;
            if (t == T_LEN - 1) *(float4*)(h_final + e) = hn;

            float t0 = tanhf(hn.x), t1 = tanhf(hn.y), t2 = tanhf(hn.z), t3 = tanhf(hn.w);
            __nv_bfloat16 h0 = __float2bfloat16(t0), h1 = __float2bfloat16(t1);
            __nv_bfloat16 h2 = __float2bfloat16(t2), h3 = __float2bfloat16(t3);
            __nv_bfloat16 l0 = __float2bfloat16(t0 - __bfloat162float(h0));
            __nv_bfloat16 l1 = __float2bfloat16(t1 - __bfloat162float(h1));
            __nv_bfloat16 l2 = __float2bfloat16(t2 - __bfloat162float(h2));
            __nv_bfloat16 l3 = __float2bfloat16(t3 - __bfloat162float(h3));
            uint2 hw, lw;
            hw.x = (uint32_t)__bfloat16_as_ushort(h0) | ((uint32_t)__bfloat16_as_ushort(h1) << 16);
            hw.y = (uint32_t)__bfloat16_as_ushort(h2) | ((uint32_t)__bfloat16_as_ushort(h3) << 16);
            lw.x = (uint32_t)__bfloat16_as_ushort(l0) | ((uint32_t)__bfloat16_as_ushort(l1) << 16);
            lw.y = (uint32_t)__bfloat16_as_ushort(l2) | ((uint32_t)__bfloat16_as_ushort(l3) << 16);
            *(uint2*)((char*)g_a_hi + (size_t)e * 2) = hw;
            *(uint2*)((char*)g_a_lo + (size_t)e * 2) = lw;
        }

        grid_bar(cta, ++epoch, &smflag);
    }
}

// ------- post (tensor cores, proven R8) --------------------------------------
__global__ void __launch_bounds__(256, 1) post_tc_kernel(
    const float* __restrict__ hid_list, const float* __restrict__ w_out,
    const float* __restrict__ b_out, float* __restrict__ out_list)
{
    extern __shared__ char sm[];
    const int tid = threadIdx.x;
    const int r0 = blockIdx.x * 128;
    const int c0 = blockIdx.y * 64;
    const int wid = tid >> 5, lane = tid & 31;
    const int wm = (wid & 3) * 32;
    const int wn = (wid >> 2) * 32;
    const int gq = lane >> 2, q = lane & 3;

    float acc[2][4][4] = {};

    const char* pAh = sm + P_AH + (wm + gq) * PITCH + q * 4;
    const char* pAl = sm + P_AL + (wm + gq) * PITCH + q * 4;
    const char* pBh = sm + P_BH + (wn + gq) * PITCH + q * 4;
    const char* pBl = sm + P_BL + (wn + gq) * PITCH + q * 4;

    for (int ch = 0; ch < 16; ch++) {
        const int kc = ch * 64;
        __syncthreads();
        #pragma unroll
        for (int i = 0; i < 8; i++) {
            int idx = i * 256 + tid;
            int r = idx >> 4, c4 = idx & 15;
            float4 v = __ldcg((const float4*)(hid_list + (size_t)(r0 + r) * H_SZ + kc + c4 * 4));
            float hx = __bfloat162float(__float2bfloat16(v.x));
            float hy = __bfloat162float(__float2bfloat16(v.y));
            float hz = __bfloat162float(__float2bfloat16(v.z));
            float hw = __bfloat162float(__float2bfloat16(v.w));
            uint2 ph = make_uint2(pack_bf16(v.x, v.y), pack_bf16(v.z, v.w));
            uint2 pl = make_uint2(pack_bf16(v.x - hx, v.y - hy), pack_bf16(v.z - hz, v.w - hw));
            *(uint2*)(sm + P_AH + r * PITCH + c4 * 8) = ph;
            *(uint2*)(sm + P_AL + r * PITCH + c4 * 8) = pl;
        }
        #pragma unroll
        for (int i = 0; i < 4; i++) {
            int idx = i * 256 + tid;
            int r = idx >> 4, c4 = idx & 15;
            float4 v = __ldcg((const float4*)(w_out + (size_t)(c0 + r) * H_SZ + kc + c4 * 4));
            float hx = __bfloat162float(__float2bfloat16(v.x));
            float hy = __bfloat162float(__float2bfloat16(v.y));
            float hz = __bfloat162float(__float2bfloat16(v.z));
            float hw = __bfloat162float(__float2bfloat16(v.w));
            uint2 ph = make_uint2(pack_bf16(v.x, v.y), pack_bf16(v.z, v.w));
            uint2 pl = make_uint2(pack_bf16(v.x - hx, v.y - hy), pack_bf16(v.z - hz, v.w - hw));
            *(uint2*)(sm + P_BH + r * PITCH + c4 * 8) = ph;
            *(uint2*)(sm + P_BL + r * PITCH + c4 * 8) = pl;
        }
        __syncthreads();

        #pragma unroll
        for (int kk = 0; kk < 4; kk++) {
            const int kb = kk * 32;
            uint32_t ah[2][4], al[2][4], bh[4][2], bl[4][2];
            #pragma unroll
            for (int mt = 0; mt < 2; mt++) {
                const int mo = mt * 16 * PITCH;
                ah[mt][0] = *(const uint32_t*)(pAh + mo + kb);
                ah[mt][1] = *(const uint32_t*)(pAh + mo + 8 * PITCH + kb);
                ah[mt][2] = *(const uint32_t*)(pAh + mo + kb + 16);
                ah[mt][3] = *(const uint32_t*)(pAh + mo + 8 * PITCH + kb + 16);
                al[mt][0] = *(const uint32_t*)(pAl + mo + kb);
                al[mt][1] = *(const uint32_t*)(pAl + mo + 8 * PITCH + kb);
                al[mt][2] = *(const uint32_t*)(pAl + mo + kb + 16);
                al[mt][3] = *(const uint32_t*)(pAl + mo + 8 * PITCH + kb + 16);
            }
            #pragma unroll
            for (int j = 0; j < 4; j++) {
                bh[j][0] = *(const uint32_t*)(pBh + j * 8 * PITCH + kb);
                bh[j][1] = *(const uint32_t*)(pBh + j * 8 * PITCH + kb + 16);
                bl[j][0] = *(const uint32_t*)(pBl + j * 8 * PITCH + kb);
                bl[j][1] = *(const uint32_t*)(pBl + j * 8 * PITCH + kb + 16);
            }
            #pragma unroll
            for (int mt = 0; mt < 2; mt++)
                #pragma unroll
                for (int j = 0; j < 4; j++) {
                    mma_bf16(acc[mt][j][0], acc[mt][j][1], acc[mt][j][2], acc[mt][j][3],
                             ah[mt][0], ah[mt][1], ah[mt][2], ah[mt][3], bh[j][0], bh[j][1]);
                    mma_bf16(acc[mt][j][0], acc[mt][j][1], acc[mt][j][2], acc[mt][j][3],
                             ah[mt][0], ah[mt][1], ah[mt][2], ah[mt][3], bl[j][0], bl[j][1]);
                    mma_bf16(acc[mt][j][0], acc[mt][j][1], acc[mt][j][2], acc[mt][j][3],
                             al[mt][0], al[mt][1], al[mt][2], al[mt][3], bh[j][0], bh[j][1]);
                }
        }
    }

    #pragma unroll
    for (int mt = 0; mt < 2; mt++) {
        #pragma unroll
        for (int j = 0; j < 4; j++) {
            int col = c0 + wn + j * 8 + q * 2;
            float b0 = b_out[col], b1 = b_out[col + 1];
            int row = r0 + wm + mt * 16 + gq;
            float2 v0, v1;
            v0.x = fminf(fmaxf(acc[mt][j][0] + b0, -20.0f), 20.0f);
            v0.y = fminf(fmaxf(acc[mt][j][1] + b1, -20.0f), 20.0f);
            v1.x = fminf(fmaxf(acc[mt][j][2] + b0, -20.0f), 20.0f);
            v1.y = fminf(fmaxf(acc[mt][j][3] + b1, -20.0f), 20.0f);
            *(float2*)(out_list + (size_t)row * NOUT + col) = v0;
            *(float2*)(out_list + (size_t)(row + 8) * NOUT + col) = v1;
        }
    }
}

extern "C" void kernel_launch(void* const* d_in, const int* in_sizes, int n_in,
                              void* d_out, int out_size) {
    const float* x       = (const float*)d_in[0];
    const float* hidden0 = (const float*)d_in[1];
    const float* noise   = (const float*)d_in[2];
    const float* w_in_w  = (const float*)d_in[3];
    const float* w_in_b  = (const float*)d_in[4];
    const float* w_hh_w  = (const float*)d_in[5];
    const float* w_hh_b  = (const float*)d_in[6];
    const float* w_out_w = (const float*)d_in[7];
    const float* w_out_b = (const float*)d_in[8];

    float* out      = (float*)d_out;
    float* hid_list = out;
    float* out_list = out + (size_t)B_SZ * T_LEN * H_SZ;
    float* h_final  = out_list + (size_t)B_SZ * T_LEN * NOUT;

    cudaFuncSetAttribute(rnn_kernel, cudaFuncAttributeMaxDynamicSharedMemorySize, SM_ALLOC);
    cudaFuncSetAttribute(post_tc_kernel, cudaFuncAttributeMaxDynamicSharedMemorySize, P_SMEM);
    init_kernel<<<(B_SZ * H_SZ + 255) / 256, 256>>>(hidden0);
    pre_kernel<<<dim3((T_LEN * B_SZ) / 64, H_SZ / 64), 256>>>(x, noise, w_in_w, w_in_b, w_hh_b);
    rnn_kernel<<<GRID_RNN, 256, SM_ALLOC>>>(hid_list, h_final, w_hh_w, hidden0);
    post_tc_kernel<<<dim3((B_SZ * T_LEN) / 128, NOUT / 64), 256, P_SMEM>>>(
        hid_list, w_out_w, w_out_b, out_list);
}

// round 10
// speedup vs baseline: 1.0184x; 1.0184x over previous
#include <cuda_runtime.h>
#include <cuda_bf16.h>
#include <math.h>
#include <stdint.h>

#define T_LEN   512
#define B_SZ    128
#define H_SZ    1024
#define NIN     128
#define NOUT    128
#define ALPHA_F 0.25f
#define LEAK_F  0.75f
#define NSCALE  0.025f
#define GRID_RNN 128
#define BH      (B_SZ * H_SZ)

// rnn SMEM (bytes): A tile 64 rows x 528B pitch, hi+lo; B tile 64 x 528, hi+lo
#define PITCH   528
#define A_HI    0
#define A_LO    33792
#define B_HI    67584
#define B_LO    101376
#define SM_ALLOC 135168

// tensorized pre/post kernels SMEM
#define P_AH   0
#define P_AL   67584
#define P_BH   135168
#define P_BL   168960
#define P_SMEM 202752

// ---------------- device scratch ----------------
__device__ float g_c[(size_t)T_LEN * BH];
__device__ __nv_bfloat16 g_a_hi[BH];
__device__ __nv_bfloat16 g_a_lo[BH];
__device__ float g_p[8 * BH];                    // 8 split-K partials (4 CTA-splits x 2 warp-sets)
__device__ unsigned g_bar_count;
__device__ unsigned g_rel[GRID_RNN * 32];

__device__ __forceinline__ void mma_bf16(float& c0, float& c1, float& c2, float& c3,
                                         uint32_t a0, uint32_t a1, uint32_t a2, uint32_t a3,
                                         uint32_t b0, uint32_t b1) {
    asm volatile(
        "mma.sync.aligned.m16n8k16.row.col.f32.bf16.bf16.f32 "
        "{%0,%1,%2,%3}, {%4,%5,%6,%7}, {%8,%9}, {%0,%1,%2,%3};"
        : "+f"(c0), "+f"(c1), "+f"(c2), "+f"(c3)
        : "r"(a0), "r"(a1), "r"(a2), "r"(a3), "r"(b0), "r"(b1));
}

__device__ __forceinline__ uint32_t pack_bf16(float a, float b) {
    __nv_bfloat16 x = __float2bfloat16(a), y = __float2bfloat16(b);
    return (uint32_t)__bfloat16_as_ushort(x) | ((uint32_t)__bfloat16_as_ushort(y) << 16);
}

// fast tanh: absolute error ~2^-22, far below the bf16-split budget
__device__ __forceinline__ float tfast(float x) {
    float e = __expf(2.0f * x);
    return 1.0f - 2.0f / (e + 1.0f);
}

// ---------------- init ----------------
__global__ void init_kernel(const float* __restrict__ hidden) {
    int i = blockIdx.x * blockDim.x + threadIdx.x;
    if (i == 0) g_bar_count = 0u;
    if (i < GRID_RNN * 32) g_rel[i] = 0u;
    if (i < BH) {
        float t = tanhf(hidden[i]);
        __nv_bfloat16 hi = __float2bfloat16(t);
        g_a_hi[i] = hi;
        g_a_lo[i] = __float2bfloat16(t - __bfloat162float(hi));
    }
}

// ------- pre (tensor cores): c = alpha*(x@Win^T + b_in + b_hh) + 0.025*noise
// CTA tile 128(rows=t*128+b) x 64(cols), K=128 in 2 chunks of 64.
// grid = (16 col-tiles, 512 row-tiles): x-fastest => 16 CTAs share the x slice.
__global__ void __launch_bounds__(256, 1) pre_tc_kernel(
    const float* __restrict__ x, const float* __restrict__ noise,
    const float* __restrict__ w_in, const float* __restrict__ b_in,
    const float* __restrict__ b_hh)
{
    extern __shared__ char sm[];
    const int tid = threadIdx.x;
    const int c0 = blockIdx.x * 64;
    const int r0 = blockIdx.y * 128;
    const int wid = tid >> 5, lane = tid & 31;
    const int wm = (wid & 3) * 32;
    const int wn = (wid >> 2) * 32;
    const int gq = lane >> 2, q = lane & 3;

    float acc[2][4][4] = {};

    const char* pAh = sm + P_AH + (wm + gq) * PITCH + q * 4;
    const char* pAl = sm + P_AL + (wm + gq) * PITCH + q * 4;
    const char* pBh = sm + P_BH + (wn + gq) * PITCH + q * 4;
    const char* pBl = sm + P_BL + (wn + gq) * PITCH + q * 4;

    #pragma unroll
    for (int ch = 0; ch < 2; ch++) {
        const int kc = ch * 64;
        __syncthreads();
        // A chunk: 128 rows x 64 cols fp32 -> bf16 hi/lo (row rr -> x[b=rr&127, t=rr>>7])
        #pragma unroll
        for (int i = 0; i < 8; i++) {
            int idx = i * 256 + tid;
            int r = idx >> 4, c4 = idx & 15;
            int rr = r0 + r;
            const float* src = x + ((size_t)(rr & 127) * T_LEN + (rr >> 7)) * NIN + kc + c4 * 4;
            float4 v = __ldcg((const float4*)src);
            float hx = __bfloat162float(__float2bfloat16(v.x));
            float hy = __bfloat162float(__float2bfloat16(v.y));
            float hz = __bfloat162float(__float2bfloat16(v.z));
            float hw = __bfloat162float(__float2bfloat16(v.w));
            *(uint2*)(sm + P_AH + r * PITCH + c4 * 8) =
                make_uint2(pack_bf16(v.x, v.y), pack_bf16(v.z, v.w));
            *(uint2*)(sm + P_AL + r * PITCH + c4 * 8) =
                make_uint2(pack_bf16(v.x - hx, v.y - hy), pack_bf16(v.z - hz, v.w - hw));
        }
        // B chunk: w_in rows c0..c0+63 x 64 cols
        #pragma unroll
        for (int i = 0; i < 4; i++) {
            int idx = i * 256 + tid;
            int r = idx >> 4, c4 = idx & 15;
            float4 v = __ldcg((const float4*)(w_in + (size_t)(c0 + r) * NIN + kc + c4 * 4));
            float hx = __bfloat162float(__float2bfloat16(v.x));
            float hy = __bfloat162float(__float2bfloat16(v.y));
            float hz = __bfloat162float(__float2bfloat16(v.z));
            float hw = __bfloat162float(__float2bfloat16(v.w));
            *(uint2*)(sm + P_BH + r * PITCH + c4 * 8) =
                make_uint2(pack_bf16(v.x, v.y), pack_bf16(v.z, v.w));
            *(uint2*)(sm + P_BL + r * PITCH + c4 * 8) =
                make_uint2(pack_bf16(v.x - hx, v.y - hy), pack_bf16(v.z - hz, v.w - hw));
        }
        __syncthreads();

        #pragma unroll
        for (int kk = 0; kk < 4; kk++) {
            const int kb = kk * 32;
            uint32_t ah[2][4], al[2][4], bhf[4][2], blf[4][2];
            #pragma unroll
            for (int mt = 0; mt < 2; mt++) {
                const int mo = mt * 16 * PITCH;
                ah[mt][0] = *(const uint32_t*)(pAh + mo + kb);
                ah[mt][1] = *(const uint32_t*)(pAh + mo + 8 * PITCH + kb);
                ah[mt][2] = *(const uint32_t*)(pAh + mo + kb + 16);
                ah[mt][3] = *(const uint32_t*)(pAh + mo + 8 * PITCH + kb + 16);
                al[mt][0] = *(const uint32_t*)(pAl + mo + kb);
                al[mt][1] = *(const uint32_t*)(pAl + mo + 8 * PITCH + kb);
                al[mt][2] = *(const uint32_t*)(pAl + mo + kb + 16);
                al[mt][3] = *(const uint32_t*)(pAl + mo + 8 * PITCH + kb + 16);
            }
            #pragma unroll
            for (int j = 0; j < 4; j++) {
                bhf[j][0] = *(const uint32_t*)(pBh + j * 8 * PITCH + kb);
                bhf[j][1] = *(const uint32_t*)(pBh + j * 8 * PITCH + kb + 16);
                blf[j][0] = *(const uint32_t*)(pBl + j * 8 * PITCH + kb);
                blf[j][1] = *(const uint32_t*)(pBl + j * 8 * PITCH + kb + 16);
            }
            #pragma unroll
            for (int mt = 0; mt < 2; mt++)
                #pragma unroll
                for (int j = 0; j < 4; j++) {
                    mma_bf16(acc[mt][j][0], acc[mt][j][1], acc[mt][j][2], acc[mt][j][3],
                             ah[mt][0], ah[mt][1], ah[mt][2], ah[mt][3], bhf[j][0], bhf[j][1]);
                    mma_bf16(acc[mt][j][0], acc[mt][j][1], acc[mt][j][2], acc[mt][j][3],
                             ah[mt][0], ah[mt][1], ah[mt][2], ah[mt][3], blf[j][0], blf[j][1]);
                    mma_bf16(acc[mt][j][0], acc[mt][j][1], acc[mt][j][2], acc[mt][j][3],
                             al[mt][0], al[mt][1], al[mt][2], al[mt][3], bhf[j][0], bhf[j][1]);
                }
        }
    }

    // epilogue: alpha*(acc + b_in + b_hh) + 0.025*noise -> g_c
    #pragma unroll
    for (int j = 0; j < 4; j++) {
        int col = c0 + wn + j * 8 + q * 2;
        float bi0 = b_in[col] + b_hh[col];
        float bi1 = b_in[col + 1] + b_hh[col + 1];
        #pragma unroll
        for (int mt = 0; mt < 2; mt++) {
            int row = r0 + wm + mt * 16 + gq;
            float2 n0 = __ldcg((const float2*)(noise + (size_t)row * H_SZ + col));
            float2 n1 = __ldcg((const float2*)(noise + (size_t)(row + 8) * H_SZ + col));
            float2 v0, v1;
            v0.x = ALPHA_F * (acc[mt][j][0] + bi0) + NSCALE * n0.x;
            v0.y = ALPHA_F * (acc[mt][j][1] + bi1) + NSCALE * n0.y;
            v1.x = ALPHA_F * (acc[mt][j][2] + bi0) + NSCALE * n1.x;
            v1.y = ALPHA_F * (acc[mt][j][3] + bi1) + NSCALE * n1.y;
            *(float2*)(g_c + (size_t)row * H_SZ + col) = v0;
            *(float2*)(g_c + (size_t)(row + 8) * H_SZ + col) = v1;
        }
    }
}

// ---- grid barrier: atomic arrival + per-CTA-line release (proven R7) ------
__device__ __forceinline__ void grid_bar(int cta, unsigned epoch, unsigned* smflag) {
    __syncthreads();
    if (threadIdx.x == 0) {
        __threadfence();
        unsigned arrived = atomicAdd(&g_bar_count, 1u) + 1u;
        *smflag = (arrived == epoch * (unsigned)GRID_RNN) ? 1u : 0u;
    }
    __syncthreads();
    if (*smflag) {
        if (threadIdx.x < GRID_RNN) {
            *(volatile unsigned*)&g_rel[threadIdx.x * 32] = epoch;
        }
    } else if (threadIdx.x == 0) {
        while (*(volatile unsigned*)&g_rel[cta * 32] < epoch) { }
        __threadfence();
    }
    __syncthreads();
}

// --------- persistent recurrent kernel: 512 threads, 2 warp-sets ------------
// 128 CTAs = 4 k-splits x 2 b-tiles x 16 h-tiles. CTA tile M=64,N=64,K=256.
// 16 warps = 2 k-sets (kk halves) x (4m x 2n grid of 16x32 warp tiles).
// Each set accumulates into its own g_p split (8 splits total).
__global__ void __launch_bounds__(512, 1) rnn_kernel(
    float* __restrict__ hid_list, float* __restrict__ h_final,
    const float* __restrict__ w_hh, const float* __restrict__ hidden0)
{
    extern __shared__ char sm[];
    __shared__ unsigned smflag;
    const int cta = blockIdx.x;
    const int ks = cta & 3;
    const int bt = (cta >> 2) & 1;
    const int ht = cta >> 3;
    const int tid = threadIdx.x;
    const int r0 = bt * 64, c0 = ht * 64, k0 = ks * 256;

    // resident weight slice -> bf16 hi/lo (once)
    for (int e = tid; e < 64 * 256; e += 512) {
        int n = e >> 8, k = e & 255;
        float w = w_hh[(size_t)(c0 + n) * H_SZ + k0 + k];
        __nv_bfloat16 wh = __float2bfloat16(w);
        __nv_bfloat16 wl = __float2bfloat16(w - __bfloat162float(wh));
        *(__nv_bfloat16*)(sm + B_HI + n * PITCH + k * 2) = wh;
        *(__nv_bfloat16*)(sm + B_LO + n * PITCH + k * 2) = wl;
    }
    __syncthreads();

    const int wid = tid >> 5, lane = tid & 31;
    const int ws = wid >> 3;              // warp-set 0/1 (kk halves)
    const int w8 = wid & 7;
    const int wm = (w8 & 3) * 16;         // 4 m-stripes of 16
    const int wn = (w8 >> 2) * 32;        // 2 n-stripes of 32
    const int gq = lane >> 2;
    const int q  = lane & 3;

    float* pout = g_p + (size_t)(ks * 2 + ws) * BH;
    const char* pAh = sm + A_HI + (wm + gq) * PITCH + q * 4;
    const char* pAl = sm + A_LO + (wm + gq) * PITCH + q * 4;
    const char* pBh = sm + B_HI + (wn + gq) * PITCH + q * 4;
    const char* pBl = sm + B_LO + (wn + gq) * PITCH + q * 4;

    const int e = cta * 1024 + tid * 2;   // update ownership (2 elems/thread)
    const int eh = e & 1023;
    float2 hreg = *(const float2*)(hidden0 + e);
    unsigned epoch = 0;

    for (int t = 0; t < T_LEN; t++) {
        float2 cv = __ldcg((const float2*)(g_c + (size_t)t * BH + e));

        // stage A slice (64 rows x 256 cols, hi+lo)
        #pragma unroll
        for (int i = 0; i < 4; i++) {
            int idx = i * 512 + tid;          // 0..2047 uint4 units
            int r = idx >> 5, cc = idx & 31;
            size_t goff = (size_t)(r0 + r) * 2048 + (size_t)k0 * 2 + cc * 16;
            uint4 vh = __ldcg((const uint4*)((const char*)g_a_hi + goff));
            uint4 vl = __ldcg((const uint4*)((const char*)g_a_lo + goff));
            *(uint4*)(sm + A_HI + r * PITCH + cc * 16) = vh;
            *(uint4*)(sm + A_LO + r * PITCH + cc * 16) = vl;
        }
        __syncthreads();

        // split-bf16 GEMM, warp-set ws handles kk in [ws*8, ws*8+8)
        float acc[4][4] = {};
        #pragma unroll
        for (int kx = 0; kx < 8; kx++) {
            const int kb = (ws * 8 + kx) * 32;
            uint32_t ah0 = *(const uint32_t*)(pAh + kb);
            uint32_t ah1 = *(const uint32_t*)(pAh + 8 * PITCH + kb);
            uint32_t ah2 = *(const uint32_t*)(pAh + kb + 16);
            uint32_t ah3 = *(const uint32_t*)(pAh + 8 * PITCH + kb + 16);
            uint32_t al0 = *(const uint32_t*)(pAl + kb);
            uint32_t al1 = *(const uint32_t*)(pAl + 8 * PITCH + kb);
            uint32_t al2 = *(const uint32_t*)(pAl + kb + 16);
            uint32_t al3 = *(const uint32_t*)(pAl + 8 * PITCH + kb + 16);
            #pragma unroll
            for (int j = 0; j < 4; j++) {
                uint32_t bh0 = *(const uint32_t*)(pBh + j * 8 * PITCH + kb);
                uint32_t bh1 = *(const uint32_t*)(pBh + j * 8 * PITCH + kb + 16);
                uint32_t bl0 = *(const uint32_t*)(pBl + j * 8 * PITCH + kb);
                uint32_t bl1 = *(const uint32_t*)(pBl + j * 8 * PITCH + kb + 16);
                mma_bf16(acc[j][0], acc[j][1], acc[j][2], acc[j][3],
                         ah0, ah1, ah2, ah3, bh0, bh1);
                mma_bf16(acc[j][0], acc[j][1], acc[j][2], acc[j][3],
                         ah0, ah1, ah2, ah3, bl0, bl1);
                mma_bf16(acc[j][0], acc[j][1], acc[j][2], acc[j][3],
                         al0, al1, al2, al3, bh0, bh1);
            }
        }
        #pragma unroll
        for (int j = 0; j < 4; j++) {
            float* pp = pout + (size_t)(r0 + wm + gq) * H_SZ + c0 + wn + j * 8 + q * 2;
            *(float2*)pp = make_float2(acc[j][0], acc[j][1]);
            *(float2*)(pp + 8 * H_SZ) = make_float2(acc[j][2], acc[j][3]);
        }

        grid_bar(cta, ++epoch, &smflag);

        // update: h' = 0.75h + 0.25*sum(8 partials) + c[t]
        {
            float2 s0 = *(const float2*)(g_p + e);
            #pragma unroll
            for (int s = 1; s < 8; s++) {
                float2 ps = *(const float2*)(g_p + (size_t)s * BH + e);
                s0.x += ps.x; s0.y += ps.y;
            }
            float2 hn;
            hn.x = LEAK_F * hreg.x + ALPHA_F * s0.x + cv.x;
            hn.y = LEAK_F * hreg.y + ALPHA_F * s0.y + cv.y;
            hreg = hn;
            *(float2*)(hid_list + ((size_t)cta * T_LEN + t) * H_SZ + eh) = hn;
            if (t == T_LEN - 1) *(float2*)(h_final + e) = hn;

            float t0 = tfast(hn.x), t1 = tfast(hn.y);
            __nv_bfloat16 h0 = __float2bfloat16(t0), h1 = __float2bfloat16(t1);
            uint32_t hw = (uint32_t)__bfloat16_as_ushort(h0) |
                          ((uint32_t)__bfloat16_as_ushort(h1) << 16);
            uint32_t lw = pack_bf16(t0 - __bfloat162float(h0), t1 - __bfloat162float(h1));
            *(uint32_t*)((char*)g_a_hi + (size_t)e * 2) = hw;
            *(uint32_t*)((char*)g_a_lo + (size_t)e * 2) = lw;
        }

        grid_bar(cta, ++epoch, &smflag);
    }
}

// ------- post (tensor cores, proven R8; grid swapped for L2 row sharing) ----
__global__ void __launch_bounds__(256, 1) post_tc_kernel(
    const float* __restrict__ hid_list, const float* __restrict__ w_out,
    const float* __restrict__ b_out, float* __restrict__ out_list)
{
    extern __shared__ char sm[];
    const int tid = threadIdx.x;
    const int c0 = blockIdx.x * 64;
    const int r0 = blockIdx.y * 128;
    const int wid = tid >> 5, lane = tid & 31;
    const int wm = (wid & 3) * 32;
    const int wn = (wid >> 2) * 32;
    const int gq = lane >> 2, q = lane & 3;

    float acc[2][4][4] = {};

    const char* pAh = sm + P_AH + (wm + gq) * PITCH + q * 4;
    const char* pAl = sm + P_AL + (wm + gq) * PITCH + q * 4;
    const char* pBh = sm + P_BH + (wn + gq) * PITCH + q * 4;
    const char* pBl = sm + P_BL + (wn + gq) * PITCH + q * 4;

    for (int ch = 0; ch < 16; ch++) {
        const int kc = ch * 64;
        __syncthreads();
        #pragma unroll
        for (int i = 0; i < 8; i++) {
            int idx = i * 256 + tid;
            int r = idx >> 4, c4 = idx & 15;
            float4 v = __ldcg((const float4*)(hid_list + (size_t)(r0 + r) * H_SZ + kc + c4 * 4));
            float hx = __bfloat162float(__float2bfloat16(v.x));
            float hy = __bfloat162float(__float2bfloat16(v.y));
            float hz = __bfloat162float(__float2bfloat16(v.z));
            float hw = __bfloat162float(__float2bfloat16(v.w));
            *(uint2*)(sm + P_AH + r * PITCH + c4 * 8) =
                make_uint2(pack_bf16(v.x, v.y), pack_bf16(v.z, v.w));
            *(uint2*)(sm + P_AL + r * PITCH + c4 * 8) =
                make_uint2(pack_bf16(v.x - hx, v.y - hy), pack_bf16(v.z - hz, v.w - hw));
        }
        #pragma unroll
        for (int i = 0; i < 4; i++) {
            int idx = i * 256 + tid;
            int r = idx >> 4, c4 = idx & 15;
            float4 v = __ldcg((const float4*)(w_out + (size_t)(c0 + r) * H_SZ + kc + c4 * 4));
            float hx = __bfloat162float(__float2bfloat16(v.x));
            float hy = __bfloat162float(__float2bfloat16(v.y));
            float hz = __bfloat162float(__float2bfloat16(v.z));
            float hw = __bfloat162float(__float2bfloat16(v.w));
            *(uint2*)(sm + P_BH + r * PITCH + c4 * 8) =
                make_uint2(pack_bf16(v.x, v.y), pack_bf16(v.z, v.w));
            *(uint2*)(sm + P_BL + r * PITCH + c4 * 8) =
                make_uint2(pack_bf16(v.x - hx, v.y - hy), pack_bf16(v.z - hz, v.w - hw));
        }
        __syncthreads();

        #pragma unroll
        for (int kk = 0; kk < 4; kk++) {
            const int kb = kk * 32;
            uint32_t ah[2][4], al[2][4], bhf[4][2], blf[4][2];
            #pragma unroll
            for (int mt = 0; mt < 2; mt++) {
                const int mo = mt * 16 * PITCH;
                ah[mt][0] = *(const uint32_t*)(pAh + mo + kb);
                ah[mt][1] = *(const uint32_t*)(pAh + mo + 8 * PITCH + kb);
                ah[mt][2] = *(const uint32_t*)(pAh + mo + kb + 16);
                ah[mt][3] = *(const uint32_t*)(pAh + mo + 8 * PITCH + kb + 16);
                al[mt][0] = *(const uint32_t*)(pAl + mo + kb);
                al[mt][1] = *(const uint32_t*)(pAl + mo + 8 * PITCH + kb);
                al[mt][2] = *(const uint32_t*)(pAl + mo + kb + 16);
                al[mt][3] = *(const uint32_t*)(pAl + mo + 8 * PITCH + kb + 16);
            }
            #pragma unroll
            for (int j = 0; j < 4; j++) {
                bhf[j][0] = *(const uint32_t*)(pBh + j * 8 * PITCH + kb);
                bhf[j][1] = *(const uint32_t*)(pBh + j * 8 * PITCH + kb + 16);
                blf[j][0] = *(const uint32_t*)(pBl + j * 8 * PITCH + kb);
                blf[j][1] = *(const uint32_t*)(pBl + j * 8 * PITCH + kb + 16);
            }
            #pragma unroll
            for (int mt = 0; mt < 2; mt++)
                #pragma unroll
                for (int j = 0; j < 4; j++) {
                    mma_bf16(acc[mt][j][0], acc[mt][j][1], acc[mt][j][2], acc[mt][j][3],
                             ah[mt][0], ah[mt][1], ah[mt][2], ah[mt][3], bhf[j][0], bhf[j][1]);
                    mma_bf16(acc[mt][j][0], acc[mt][j][1], acc[mt][j][2], acc[mt][j][3],
                             ah[mt][0], ah[mt][1], ah[mt][2], ah[mt][3], blf[j][0], blf[j][1]);
                    mma_bf16(acc[mt][j][0], acc[mt][j][1], acc[mt][j][2], acc[mt][j][3],
                             al[mt][0], al[mt][1], al[mt][2], al[mt][3], bhf[j][0], bhf[j][1]);
                }
        }
    }

    #pragma unroll
    for (int mt = 0; mt < 2; mt++) {
        #pragma unroll
        for (int j = 0; j < 4; j++) {
            int col = c0 + wn + j * 8 + q * 2;
            float b0 = b_out[col], b1 = b_out[col + 1];
            int row = r0 + wm + mt * 16 + gq;
            float2 v0, v1;
            v0.x = fminf(fmaxf(acc[mt][j][0] + b0, -20.0f), 20.0f);
            v0.y = fminf(fmaxf(acc[mt][j][1] + b1, -20.0f), 20.0f);
            v1.x = fminf(fmaxf(acc[mt][j][2] + b0, -20.0f), 20.0f);
            v1.y = fminf(fmaxf(acc[mt][j][3] + b1, -20.0f), 20.0f);
            *(float2*)(out_list + (size_t)row * NOUT + col) = v0;
            *(float2*)(out_list + (size_t)(row + 8) * NOUT + col) = v1;
        }
    }
}

extern "C" void kernel_launch(void* const* d_in, const int* in_sizes, int n_in,
                              void* d_out, int out_size) {
    const float* x       = (const float*)d_in[0];
    const float* hidden0 = (const float*)d_in[1];
    const float* noise   = (const float*)d_in[2];
    const float* w_in_w  = (const float*)d_in[3];
    const float* w_in_b  = (const float*)d_in[4];
    const float* w_hh_w  = (const float*)d_in[5];
    const float* w_hh_b  = (const float*)d_in[6];
    const float* w_out_w = (const float*)d_in[7];
    const float* w_out_b = (const float*)d_in[8];

    float* out      = (float*)d_out;
    float* hid_list = out;
    float* out_list = out + (size_t)B_SZ * T_LEN * H_SZ;
    float* h_final  = out_list + (size_t)B_SZ * T_LEN * NOUT;

    cudaFuncSetAttribute(rnn_kernel, cudaFuncAttributeMaxDynamicSharedMemorySize, SM_ALLOC);
    cudaFuncSetAttribute(pre_tc_kernel, cudaFuncAttributeMaxDynamicSharedMemorySize, P_SMEM);
    cudaFuncSetAttribute(post_tc_kernel, cudaFuncAttributeMaxDynamicSharedMemorySize, P_SMEM);
    init_kernel<<<(BH + 255) / 256, 256>>>(hidden0);
    pre_tc_kernel<<<dim3(H_SZ / 64, (T_LEN * B_SZ) / 128), 256, P_SMEM>>>(
        x, noise, w_in_w, w_in_b, w_hh_b);
    rnn_kernel<<<GRID_RNN, 512, SM_ALLOC>>>(hid_list, h_final, w_hh_w, hidden0);
    post_tc_kernel<<<dim3(NOUT / 64, (B_SZ * T_LEN) / 128), 256, P_SMEM>>>(
        hid_list, w_out_w, w_out_b, out_list);
}

// round 11
// speedup vs baseline: 1.0723x; 1.0529x over previous
#include <cuda_runtime.h>
#include <cuda_bf16.h>
#include <math.h>
#include <stdint.h>

#define T_LEN   512
#define B_SZ    128
#define H_SZ    1024
#define NIN     128
#define NOUT    128
#define ALPHA_F 0.25f
#define LEAK_F  0.75f
#define NSCALE  0.025f
#define GRID_RNN 128
#define BH      (B_SZ * H_SZ)

// rnn SMEM (bytes): A tile 64 rows x 528B pitch hi+lo; B tile 64 x 528 hi+lo
#define PITCH  528
#define A_HI   0
#define A_LO   33792
#define B_HI   67584
#define B_LO   101376
#define SM_ALLOC 135168

// tensorized pre/post kernels SMEM
#define P_AH   0
#define P_AL   67584
#define P_BH   135168
#define P_BL   168960
#define P_SMEM 202752

// ---------------- device scratch ----------------
__device__ float g_c[(size_t)T_LEN * BH];
__device__ __nv_bfloat16 g_a_hi[BH];
__device__ __nv_bfloat16 g_a_lo[BH];
__device__ float g_p[4 * BH];                    // 4 split-K partials
__device__ unsigned g_bar_count;
__device__ unsigned g_rel[GRID_RNN * 32];

__device__ __forceinline__ void mma_bf16(float& c0, float& c1, float& c2, float& c3,
                                         uint32_t a0, uint32_t a1, uint32_t a2, uint32_t a3,
                                         uint32_t b0, uint32_t b1) {
    asm volatile(
        "mma.sync.aligned.m16n8k16.row.col.f32.bf16.bf16.f32 "
        "{%0,%1,%2,%3}, {%4,%5,%6,%7}, {%8,%9}, {%0,%1,%2,%3};"
        : "+f"(c0), "+f"(c1), "+f"(c2), "+f"(c3)
        : "r"(a0), "r"(a1), "r"(a2), "r"(a3), "r"(b0), "r"(b1));
}

__device__ __forceinline__ uint32_t pack_bf16(float a, float b) {
    __nv_bfloat16 x = __float2bfloat16(a), y = __float2bfloat16(b);
    return (uint32_t)__bfloat16_as_ushort(x) | ((uint32_t)__bfloat16_as_ushort(y) << 16);
}

// ---------------- init ----------------
__global__ void init_kernel(const float* __restrict__ hidden) {
    int i = blockIdx.x * blockDim.x + threadIdx.x;
    if (i == 0) g_bar_count = 0u;
    if (i < GRID_RNN * 32) g_rel[i] = 0u;
    if (i < BH) {
        float t = tanhf(hidden[i]);
        __nv_bfloat16 hi = __float2bfloat16(t);
        g_a_hi[i] = hi;
        g_a_lo[i] = __float2bfloat16(t - __bfloat162float(hi));
    }
}

// ------- pre (tensor cores): c = alpha*(x@Win^T + b_in + b_hh) + 0.025*noise
// CTA tile 128(rows=t*128+b) x 64(cols), K=128 in 2 chunks of 64.
__global__ void __launch_bounds__(256, 1) pre_tc_kernel(
    const float* __restrict__ x, const float* __restrict__ noise,
    const float* __restrict__ w_in, const float* __restrict__ b_in,
    const float* __restrict__ b_hh)
{
    extern __shared__ char sm[];
    const int tid = threadIdx.x;
    const int c0 = blockIdx.x * 64;
    const int r0 = blockIdx.y * 128;
    const int wid = tid >> 5, lane = tid & 31;
    const int wm = (wid & 3) * 32;
    const int wn = (wid >> 2) * 32;
    const int gq = lane >> 2, q = lane & 3;

    float acc[2][4][4] = {};

    const char* pAh = sm + P_AH + (wm + gq) * PITCH + q * 4;
    const char* pAl = sm + P_AL + (wm + gq) * PITCH + q * 4;
    const char* pBh = sm + P_BH + (wn + gq) * PITCH + q * 4;
    const char* pBl = sm + P_BL + (wn + gq) * PITCH + q * 4;

    #pragma unroll
    for (int ch = 0; ch < 2; ch++) {
        const int kc = ch * 64;
        __syncthreads();
        #pragma unroll
        for (int i = 0; i < 8; i++) {
            int idx = i * 256 + tid;
            int r = idx >> 4, c4 = idx & 15;
            int rr = r0 + r;
            const float* src = x + ((size_t)(rr & 127) * T_LEN + (rr >> 7)) * NIN + kc + c4 * 4;
            float4 v = __ldcg((const float4*)src);
            float hx = __bfloat162float(__float2bfloat16(v.x));
            float hy = __bfloat162float(__float2bfloat16(v.y));
            float hz = __bfloat162float(__float2bfloat16(v.z));
            float hw = __bfloat162float(__float2bfloat16(v.w));
            *(uint2*)(sm + P_AH + r * PITCH + c4 * 8) =
                make_uint2(pack_bf16(v.x, v.y), pack_bf16(v.z, v.w));
            *(uint2*)(sm + P_AL + r * PITCH + c4 * 8) =
                make_uint2(pack_bf16(v.x - hx, v.y - hy), pack_bf16(v.z - hz, v.w - hw));
        }
        #pragma unroll
        for (int i = 0; i < 4; i++) {
            int idx = i * 256 + tid;
            int r = idx >> 4, c4 = idx & 15;
            float4 v = __ldcg((const float4*)(w_in + (size_t)(c0 + r) * NIN + kc + c4 * 4));
            float hx = __bfloat162float(__float2bfloat16(v.x));
            float hy = __bfloat162float(__float2bfloat16(v.y));
            float hz = __bfloat162float(__float2bfloat16(v.z));
            float hw = __bfloat162float(__float2bfloat16(v.w));
            *(uint2*)(sm + P_BH + r * PITCH + c4 * 8) =
                make_uint2(pack_bf16(v.x, v.y), pack_bf16(v.z, v.w));
            *(uint2*)(sm + P_BL + r * PITCH + c4 * 8) =
                make_uint2(pack_bf16(v.x - hx, v.y - hy), pack_bf16(v.z - hz, v.w - hw));
        }
        __syncthreads();

        #pragma unroll
        for (int kk = 0; kk < 4; kk++) {
            const int kb = kk * 32;
            uint32_t ah[2][4], al[2][4], bhf[4][2], blf[4][2];
            #pragma unroll
            for (int mt = 0; mt < 2; mt++) {
                const int mo = mt * 16 * PITCH;
                ah[mt][0] = *(const uint32_t*)(pAh + mo + kb);
                ah[mt][1] = *(const uint32_t*)(pAh + mo + 8 * PITCH + kb);
                ah[mt][2] = *(const uint32_t*)(pAh + mo + kb + 16);
                ah[mt][3] = *(const uint32_t*)(pAh + mo + 8 * PITCH + kb + 16);
                al[mt][0] = *(const uint32_t*)(pAl + mo + kb);
                al[mt][1] = *(const uint32_t*)(pAl + mo + 8 * PITCH + kb);
                al[mt][2] = *(const uint32_t*)(pAl + mo + kb + 16);
                al[mt][3] = *(const uint32_t*)(pAl + mo + 8 * PITCH + kb + 16);
            }
            #pragma unroll
            for (int j = 0; j < 4; j++) {
                bhf[j][0] = *(const uint32_t*)(pBh + j * 8 * PITCH + kb);
                bhf[j][1] = *(const uint32_t*)(pBh + j * 8 * PITCH + kb + 16);
                blf[j][0] = *(const uint32_t*)(pBl + j * 8 * PITCH + kb);
                blf[j][1] = *(const uint32_t*)(pBl + j * 8 * PITCH + kb + 16);
            }
            #pragma unroll
            for (int mt = 0; mt < 2; mt++)
                #pragma unroll
                for (int j = 0; j < 4; j++) {
                    mma_bf16(acc[mt][j][0], acc[mt][j][1], acc[mt][j][2], acc[mt][j][3],
                             ah[mt][0], ah[mt][1], ah[mt][2], ah[mt][3], bhf[j][0], bhf[j][1]);
                    mma_bf16(acc[mt][j][0], acc[mt][j][1], acc[mt][j][2], acc[mt][j][3],
                             ah[mt][0], ah[mt][1], ah[mt][2], ah[mt][3], blf[j][0], blf[j][1]);
                    mma_bf16(acc[mt][j][0], acc[mt][j][1], acc[mt][j][2], acc[mt][j][3],
                             al[mt][0], al[mt][1], al[mt][2], al[mt][3], bhf[j][0], bhf[j][1]);
                }
        }
    }

    #pragma unroll
    for (int j = 0; j < 4; j++) {
        int col = c0 + wn + j * 8 + q * 2;
        float bi0 = b_in[col] + b_hh[col];
        float bi1 = b_in[col + 1] + b_hh[col + 1];
        #pragma unroll
        for (int mt = 0; mt < 2; mt++) {
            int row = r0 + wm + mt * 16 + gq;
            float2 n0 = __ldcg((const float2*)(noise + (size_t)row * H_SZ + col));
            float2 n1 = __ldcg((const float2*)(noise + (size_t)(row + 8) * H_SZ + col));
            float2 v0, v1;
            v0.x = ALPHA_F * (acc[mt][j][0] + bi0) + NSCALE * n0.x;
            v0.y = ALPHA_F * (acc[mt][j][1] + bi1) + NSCALE * n0.y;
            v1.x = ALPHA_F * (acc[mt][j][2] + bi0) + NSCALE * n1.x;
            v1.y = ALPHA_F * (acc[mt][j][3] + bi1) + NSCALE * n1.y;
            *(float2*)(g_c + (size_t)row * H_SZ + col) = v0;
            *(float2*)(g_c + (size_t)(row + 8) * H_SZ + col) = v1;
        }
    }
}

// ---- grid barrier: atomic arrival + per-CTA-line release (proven R7/R8) ---
__device__ __forceinline__ void grid_bar(int cta, unsigned epoch, unsigned* smflag) {
    __syncthreads();
    if (threadIdx.x == 0) {
        __threadfence();
        unsigned arrived = atomicAdd(&g_bar_count, 1u) + 1u;
        *smflag = (arrived == epoch * (unsigned)GRID_RNN) ? 1u : 0u;
    }
    __syncthreads();
    if (*smflag) {
        if (threadIdx.x < GRID_RNN) {
            *(volatile unsigned*)&g_rel[threadIdx.x * 32] = epoch;
        }
    } else if (threadIdx.x == 0) {
        while (*(volatile unsigned*)&g_rel[cta * 32] < epoch) { }
        __threadfence();
    }
    __syncthreads();
}

// ---------------- persistent recurrent kernel (exact R8 structure) ----------
// 128 CTAs = 4 k-splits x 2 b-tiles x 16 h-tiles. 256 threads, 8 warps 16x32.
__global__ void __launch_bounds__(256, 1) rnn_kernel(
    float* __restrict__ hid_list, float* __restrict__ h_final,
    const float* __restrict__ w_hh, const float* __restrict__ hidden0)
{
    extern __shared__ char sm[];
    __shared__ unsigned smflag;
    const int cta = blockIdx.x;
    const int ks = cta & 3;
    const int bt = (cta >> 2) & 1;
    const int ht = cta >> 3;
    const int tid = threadIdx.x;
    const int r0 = bt * 64, c0 = ht * 64, k0 = ks * 256;

    for (int e = tid; e < 64 * 256; e += 256) {
        int n = e >> 8, k = e & 255;
        float w = w_hh[(size_t)(c0 + n) * H_SZ + k0 + k];
        __nv_bfloat16 wh = __float2bfloat16(w);
        __nv_bfloat16 wl = __float2bfloat16(w - __bfloat162float(wh));
        *(__nv_bfloat16*)(sm + B_HI + n * PITCH + k * 2) = wh;
        *(__nv_bfloat16*)(sm + B_LO + n * PITCH + k * 2) = wl;
    }
    __syncthreads();

    const int wid = tid >> 5, lane = tid & 31;
    const int wm = (wid & 3) * 16;
    const int wn = (wid >> 2) * 32;
    const int gq = lane >> 2;
    const int q  = lane & 3;

    float* pout = g_p + (size_t)ks * BH;
    const char* pAh = sm + A_HI + (wm + gq) * PITCH + q * 4;
    const char* pAl = sm + A_LO + (wm + gq) * PITCH + q * 4;
    const char* pBh = sm + B_HI + (wn + gq) * PITCH + q * 4;
    const char* pBl = sm + B_LO + (wn + gq) * PITCH + q * 4;

    const int e  = cta * 1024 + tid * 4;
    const int eb = e >> 10, eh = e & 1023;

    float4 hreg = *(const float4*)(hidden0 + e);
    unsigned epoch = 0;

    for (int t = 0; t < T_LEN; t++) {
        float4 cv = __ldcg((const float4*)(g_c + (size_t)t * BH + e));

        #pragma unroll
        for (int i = 0; i < 8; i++) {
            int idx = i * 256 + tid;
            int r = idx >> 5, cc = idx & 31;
            size_t goff = (size_t)(r0 + r) * 2048 + (size_t)k0 * 2 + cc * 16;
            uint4 vh = __ldcg((const uint4*)((const char*)g_a_hi + goff));
            uint4 vl = __ldcg((const uint4*)((const char*)g_a_lo + goff));
            *(uint4*)(sm + A_HI + r * PITCH + cc * 16) = vh;
            *(uint4*)(sm + A_LO + r * PITCH + cc * 16) = vl;
        }
        __syncthreads();

        float acc[4][4] = {};
        #pragma unroll
        for (int kk = 0; kk < 16; kk++) {
            const int kb = kk * 32;
            uint32_t ah0 = *(const uint32_t*)(pAh + kb);
            uint32_t ah1 = *(const uint32_t*)(pAh + 8 * PITCH + kb);
            uint32_t ah2 = *(const uint32_t*)(pAh + kb + 16);
            uint32_t ah3 = *(const uint32_t*)(pAh + 8 * PITCH + kb + 16);
            uint32_t al0 = *(const uint32_t*)(pAl + kb);
            uint32_t al1 = *(const uint32_t*)(pAl + 8 * PITCH + kb);
            uint32_t al2 = *(const uint32_t*)(pAl + kb + 16);
            uint32_t al3 = *(const uint32_t*)(pAl + 8 * PITCH + kb + 16);
            #pragma unroll
            for (int j = 0; j < 4; j++) {
                uint32_t bh0 = *(const uint32_t*)(pBh + j * 8 * PITCH + kb);
                uint32_t bh1 = *(const uint32_t*)(pBh + j * 8 * PITCH + kb + 16);
                uint32_t bl0 = *(const uint32_t*)(pBl + j * 8 * PITCH + kb);
                uint32_t bl1 = *(const uint32_t*)(pBl + j * 8 * PITCH + kb + 16);
                mma_bf16(acc[j][0], acc[j][1], acc[j][2], acc[j][3],
                         ah0, ah1, ah2, ah3, bh0, bh1);
                mma_bf16(acc[j][0], acc[j][1], acc[j][2], acc[j][3],
                         ah0, ah1, ah2, ah3, bl0, bl1);
                mma_bf16(acc[j][0], acc[j][1], acc[j][2], acc[j][3],
                         al0, al1, al2, al3, bh0, bh1);
            }
        }
        #pragma unroll
        for (int j = 0; j < 4; j++) {
            float* pp = pout + (size_t)(r0 + wm + gq) * H_SZ + c0 + wn + j * 8 + q * 2;
            *(float2*)pp = make_float2(acc[j][0], acc[j][1]);
            *(float2*)(pp + 8 * H_SZ) = make_float2(acc[j][2], acc[j][3]);
        }

        grid_bar(cta, ++epoch, &smflag);

        {
            float4 p0 = *(const float4*)(g_p + e);
            float4 p1 = *(const float4*)(g_p + 1 * BH + e);
            float4 p2 = *(const float4*)(g_p + 2 * BH + e);
            float4 p3 = *(const float4*)(g_p + 3 * BH + e);
            float4 hn;
            hn.x = LEAK_F * hreg.x + ALPHA_F * (p0.x + p1.x + p2.x + p3.x) + cv.x;
            hn.y = LEAK_F * hreg.y + ALPHA_F * (p0.y + p1.y + p2.y + p3.y) + cv.y;
            hn.z = LEAK_F * hreg.z + ALPHA_F * (p0.z + p1.z + p2.z + p3.z) + cv.z;
            hn.w = LEAK_F * hreg.w + ALPHA_F * (p0.w + p1.w + p2.w + p3.w) + cv.w;
            hreg = hn;
            *(float4*)(hid_list + ((size_t)eb * T_LEN + t) * H_SZ + eh) = hn;
            if (t == T_LEN - 1) *(float4*)(h_final + e) = hn;

            float t0 = tanhf(hn.x), t1 = tanhf(hn.y), t2 = tanhf(hn.z), t3 = tanhf(hn.w);
            __nv_bfloat16 h0 = __float2bfloat16(t0), h1 = __float2bfloat16(t1);
            __nv_bfloat16 h2 = __float2bfloat16(t2), h3 = __float2bfloat16(t3);
            __nv_bfloat16 l0 = __float2bfloat16(t0 - __bfloat162float(h0));
            __nv_bfloat16 l1 = __float2bfloat16(t1 - __bfloat162float(h1));
            __nv_bfloat16 l2 = __float2bfloat16(t2 - __bfloat162float(h2));
            __nv_bfloat16 l3 = __float2bfloat16(t3 - __bfloat162float(h3));
            uint2 hw, lw;
            hw.x = (uint32_t)__bfloat16_as_ushort(h0) | ((uint32_t)__bfloat16_as_ushort(h1) << 16);
            hw.y = (uint32_t)__bfloat16_as_ushort(h2) | ((uint32_t)__bfloat16_as_ushort(h3) << 16);
            lw.x = (uint32_t)__bfloat16_as_ushort(l0) | ((uint32_t)__bfloat16_as_ushort(l1) << 16);
            lw.y = (uint32_t)__bfloat16_as_ushort(l2) | ((uint32_t)__bfloat16_as_ushort(l3) << 16);
            *(uint2*)((char*)g_a_hi + (size_t)e * 2) = hw;
            *(uint2*)((char*)g_a_lo + (size_t)e * 2) = lw;
        }

        grid_bar(cta, ++epoch, &smflag);
    }
}

// ------- post (tensor cores, grid-swapped for L2 row sharing) ---------------
__global__ void __launch_bounds__(256, 1) post_tc_kernel(
    const float* __restrict__ hid_list, const float* __restrict__ w_out,
    const float* __restrict__ b_out, float* __restrict__ out_list)
{
    extern __shared__ char sm[];
    const int tid = threadIdx.x;
    const int c0 = blockIdx.x * 64;
    const int r0 = blockIdx.y * 128;
    const int wid = tid >> 5, lane = tid & 31;
    const int wm = (wid & 3) * 32;
    const int wn = (wid >> 2) * 32;
    const int gq = lane >> 2, q = lane & 3;

    float acc[2][4][4] = {};

    const char* pAh = sm + P_AH + (wm + gq) * PITCH + q * 4;
    const char* pAl = sm + P_AL + (wm + gq) * PITCH + q * 4;
    const char* pBh = sm + P_BH + (wn + gq) * PITCH + q * 4;
    const char* pBl = sm + P_BL + (wn + gq) * PITCH + q * 4;

    for (int ch = 0; ch < 16; ch++) {
        const int kc = ch * 64;
        __syncthreads();
        #pragma unroll
        for (int i = 0; i < 8; i++) {
            int idx = i * 256 + tid;
            int r = idx >> 4, c4 = idx & 15;
            float4 v = __ldcg((const float4*)(hid_list + (size_t)(r0 + r) * H_SZ + kc + c4 * 4));
            float hx = __bfloat162float(__float2bfloat16(v.x));
            float hy = __bfloat162float(__float2bfloat16(v.y));
            float hz = __bfloat162float(__float2bfloat16(v.z));
            float hw = __bfloat162float(__float2bfloat16(v.w));
            *(uint2*)(sm + P_AH + r * PITCH + c4 * 8) =
                make_uint2(pack_bf16(v.x, v.y), pack_bf16(v.z, v.w));
            *(uint2*)(sm + P_AL + r * PITCH + c4 * 8) =
                make_uint2(pack_bf16(v.x - hx, v.y - hy), pack_bf16(v.z - hz, v.w - hw));
        }
        #pragma unroll
        for (int i = 0; i < 4; i++) {
            int idx = i * 256 + tid;
            int r = idx >> 4, c4 = idx & 15;
            float4 v = __ldcg((const float4*)(w_out + (size_t)(c0 + r) * H_SZ + kc + c4 * 4));
            float hx = __bfloat162float(__float2bfloat16(v.x));
            float hy = __bfloat162float(__float2bfloat16(v.y));
            float hz = __bfloat162float(__float2bfloat16(v.z));
            float hw = __bfloat162float(__float2bfloat16(v.w));
            *(uint2*)(sm + P_BH + r * PITCH + c4 * 8) =
                make_uint2(pack_bf16(v.x, v.y), pack_bf16(v.z, v.w));
            *(uint2*)(sm + P_BL + r * PITCH + c4 * 8) =
                make_uint2(pack_bf16(v.x - hx, v.y - hy), pack_bf16(v.z - hz, v.w - hw));
        }
        __syncthreads();

        #pragma unroll
        for (int kk = 0; kk < 4; kk++) {
            const int kb = kk * 32;
            uint32_t ah[2][4], al[2][4], bhf[4][2], blf[4][2];
            #pragma unroll
            for (int mt = 0; mt < 2; mt++) {
                const int mo = mt * 16 * PITCH;
                ah[mt][0] = *(const uint32_t*)(pAh + mo + kb);
                ah[mt][1] = *(const uint32_t*)(pAh + mo + 8 * PITCH + kb);
                ah[mt][2] = *(const uint32_t*)(pAh + mo + kb + 16);
                ah[mt][3] = *(const uint32_t*)(pAh + mo + 8 * PITCH + kb + 16);
                al[mt][0] = *(const uint32_t*)(pAl + mo + kb);
                al[mt][1] = *(const uint32_t*)(pAl + mo + 8 * PITCH + kb);
                al[mt][2] = *(const uint32_t*)(pAl + mo + kb + 16);
                al[mt][3] = *(const uint32_t*)(pAl + mo + 8 * PITCH + kb + 16);
            }
            #pragma unroll
            for (int j = 0; j < 4; j++) {
                bhf[j][0] = *(const uint32_t*)(pBh + j * 8 * PITCH + kb);
                bhf[j][1] = *(const uint32_t*)(pBh + j * 8 * PITCH + kb + 16);
                blf[j][0] = *(const uint32_t*)(pBl + j * 8 * PITCH + kb);
                blf[j][1] = *(const uint32_t*)(pBl + j * 8 * PITCH + kb + 16);
            }
            #pragma unroll
            for (int mt = 0; mt < 2; mt++)
                #pragma unroll
                for (int j = 0; j < 4; j++) {
                    mma_bf16(acc[mt][j][0], acc[mt][j][1], acc[mt][j][2], acc[mt][j][3],
                             ah[mt][0], ah[mt][1], ah[mt][2], ah[mt][3], bhf[j][0], bhf[j][1]);
                    mma_bf16(acc[mt][j][0], acc[mt][j][1], acc[mt][j][2], acc[mt][j][3],
                             ah[mt][0], ah[mt][1], ah[mt][2], ah[mt][3], blf[j][0], blf[j][1]);
                    mma_bf16(acc[mt][j][0], acc[mt][j][1], acc[mt][j][2], acc[mt][j][3],
                             al[mt][0], al[mt][1], al[mt][2], al[mt][3], bhf[j][0], bhf[j][1]);
                }
        }
    }

    #pragma unroll
    for (int mt = 0; mt < 2; mt++) {
        #pragma unroll
        for (int j = 0; j < 4; j++) {
            int col = c0 + wn + j * 8 + q * 2;
            float b0 = b_out[col], b1 = b_out[col + 1];
            int row = r0 + wm + mt * 16 + gq;
            float2 v0, v1;
            v0.x = fminf(fmaxf(acc[mt][j][0] + b0, -20.0f), 20.0f);
            v0.y = fminf(fmaxf(acc[mt][j][1] + b1, -20.0f), 20.0f);
            v1.x = fminf(fmaxf(acc[mt][j][2] + b0, -20.0f), 20.0f);
            v1.y = fminf(fmaxf(acc[mt][j][3] + b1, -20.0f), 20.0f);
            *(float2*)(out_list + (size_t)row * NOUT + col) = v0;
            *(float2*)(out_list + (size_t)(row + 8) * NOUT + col) = v1;
        }
    }
}

extern "C" void kernel_launch(void* const* d_in, const int* in_sizes, int n_in,
                              void* d_out, int out_size) {
    const float* x       = (const float*)d_in[0];
    const float* hidden0 = (const float*)d_in[1];
    const float* noise   = (const float*)d_in[2];
    const float* w_in_w  = (const float*)d_in[3];
    const float* w_in_b  = (const float*)d_in[4];
    const float* w_hh_w  = (const float*)d_in[5];
    const float* w_hh_b  = (const float*)d_in[6];
    const float* w_out_w = (const float*)d_in[7];
    const float* w_out_b = (const float*)d_in[8];

    float* out      = (float*)d_out;
    float* hid_list = out;
    float* out_list = out + (size_t)B_SZ * T_LEN * H_SZ;
    float* h_final  = out_list + (size_t)B_SZ * T_LEN * NOUT;

    cudaFuncSetAttribute(rnn_kernel, cudaFuncAttributeMaxDynamicSharedMemorySize, SM_ALLOC);
    cudaFuncSetAttribute(pre_tc_kernel, cudaFuncAttributeMaxDynamicSharedMemorySize, P_SMEM);
    cudaFuncSetAttribute(post_tc_kernel, cudaFuncAttributeMaxDynamicSharedMemorySize, P_SMEM);
    init_kernel<<<(BH + 255) / 256, 256>>>(hidden0);
    pre_tc_kernel<<<dim3(H_SZ / 64, (T_LEN * B_SZ) / 128), 256, P_SMEM>>>(
        x, noise, w_in_w, w_in_b, w_hh_b);
    rnn_kernel<<<GRID_RNN, 256, SM_ALLOC>>>(hid_list, h_final, w_hh_w, hidden0);
    post_tc_kernel<<<dim3(NOUT / 64, (B_SZ * T_LEN) / 128), 256, P_SMEM>>>(
        hid_list, w_out_w, w_out_b, out_list);
}